// round 16
// baseline (speedup 1.0000x reference)
#include <cuda_runtime.h>
#include <cuda_fp16.h>
#include <cstdint>
#include <cstddef>
#include <type_traits>

// ---------------- problem constants ----------------
#define BDIM 4
#define SLEN 4096
#define DIMX 1024
#define EI   1536
#define HGW  3072
#define NC   32
#define CL   128              // SLEN/NC
#define MTOT (BDIM*SLEN)      // 16384

// ---------------- scratch (device globals; no allocation) ----------------
__device__ __half g_hg [(size_t)MTOT * HGW];   // GEMM1 output [16384,3072] fp16
__device__ __half g_xh [(size_t)MTOT * DIMX];  // fp16 x
__device__ __half g_wh [(size_t)HGW * DIMX];   // fp16 W_hg
__device__ __half g_uh [(size_t)DIMX * EI];    // fp16 W_out
__device__ __half g_hsh[(size_t)MTOT * EI];    // fp16 hsum = hf+hb
__device__ float  g_cA[2 * BDIM * NC * EI];
__device__ float  g_cB[2 * BDIM * NC * EI];
__device__ float  g_cI[2 * BDIM * NC * EI];

// ---------------- helpers ----------------
__device__ __forceinline__ uint32_t s2u(const void* p) {
    uint32_t a;
    asm("{ .reg .u64 t; cvta.to.shared.u64 t, %1; cvt.u32.u64 %0, t; }" : "=r"(a) : "l"(p));
    return a;
}
__device__ __forceinline__ void cp16(uint32_t dst, const void* src) {
    asm volatile("cp.async.cg.shared.global [%0], [%1], 16;" :: "r"(dst), "l"(src) : "memory");
}
__device__ __forceinline__ void cp_commit() {
    asm volatile("cp.async.commit_group;" ::: "memory");
}
__device__ __forceinline__ void cp_wait1() {
    asm volatile("cp.async.wait_group 1;" ::: "memory");
}
__device__ __forceinline__ void mma_f16(float c[4], const uint32_t a[4], const uint32_t b[2]) {
    asm volatile(
        "mma.sync.aligned.m16n8k16.row.col.f32.f16.f16.f32 "
        "{%0,%1,%2,%3}, {%4,%5,%6,%7}, {%8,%9}, {%0,%1,%2,%3};\n"
        : "+f"(c[0]), "+f"(c[1]), "+f"(c[2]), "+f"(c[3])
        : "r"(a[0]), "r"(a[1]), "r"(a[2]), "r"(a[3]), "r"(b[0]), "r"(b[1]));
}
__device__ __forceinline__ void ldsm4(uint32_t& d0, uint32_t& d1, uint32_t& d2, uint32_t& d3,
                                      uint32_t a) {
    asm volatile("ldmatrix.sync.aligned.m8n8.x4.shared.b16 {%0,%1,%2,%3}, [%4];"
                 : "=r"(d0), "=r"(d1), "=r"(d2), "=r"(d3) : "r"(a));
}

// ---------------- GEMM: C[M,N] = A[M,K] * B[N,K]^T  (fp16 operands, fp32 accum)
// BM=128, BN template (256 for GEMM1, 128 for GEMM2), BK=64 halfs,
// 3-stage cp.async pipeline, 256 threads = 8 warps of 64 x (BN/4).
// Fragments via ldmatrix.x4, double-buffered across k16 steps.
#define GBM 128
#define GBK 64                          // halfs per K block (128 bytes)
#define LDH 72                          // halfs per smem row (144B)
#define SA_B (GBM * LDH * 2)            // 18432 B

template <int BN, typename OutT>
__global__ void __launch_bounds__(256, 1)
gemm_fp16(const __half* __restrict__ A, const __half* __restrict__ B,
          OutT* __restrict__ C, int N, int K)
{
    constexpr int SB_B = BN * LDH * 2;
    constexpr int SS_B = SA_B + SB_B;
    constexpr int NI   = BN / 32;       // n-tiles per warp (8 or 4)
    constexpr int NP   = BN / 64;       // ldsm.x4 B loads per warp (4 or 2)

    extern __shared__ __align__(16) char smc[];
    const uint32_t sbase = s2u(smc);

    const int tid  = threadIdx.x;
    const int lane = tid & 31;
    const int warp = tid >> 5;
    const int wm = (warp >> 2) << 6;           // 0, 64
    const int wn = (warp & 3) * (BN / 4);      // warp n offset
    const int g  = lane >> 2;
    const int q  = lane & 3;

    const int m0 = blockIdx.y << 7;
    const int n0 = blockIdx.x * BN;
    const int KT = K >> 6;             // K / 64

    const int arow = tid >> 3;          // 0..31
    const int chk  = tid & 7;
    const __half* Abase = A + (size_t)(m0 + arow) * K + chk * 8;
    const __half* Bbase = B + (size_t)(n0 + arow) * K + chk * 8;

    auto ISSUE = [&](int kt, int st) {
        const uint32_t sa = sbase + (uint32_t)st * SS_B;
        const uint32_t sb = sa + SA_B;
        const size_t ko = (size_t)kt * GBK;
#pragma unroll
        for (int j = 0; j < 4; j++)
            cp16(sa + (uint32_t)((arow + 32 * j) * LDH + chk * 8) * 2,
                 Abase + (size_t)(32 * j) * K + ko);
#pragma unroll
        for (int j = 0; j < BN / 32; j++)
            cp16(sb + (uint32_t)((arow + 32 * j) * LDH + chk * 8) * 2,
                 Bbase + (size_t)(32 * j) * K + ko);
        cp_commit();
    };

    // ldmatrix per-lane base byte offsets (relative to stage base)
    const int aRow = wm + (lane & 15);
    const int aK   = (lane & 16) ? 8 : 0;
    uint32_t aOff[4];
#pragma unroll
    for (int mi = 0; mi < 4; mi++)
        aOff[mi] = (uint32_t)(((aRow + mi * 16) * LDH + aK) * 2);
    const int bRow = wn + (lane & 7) + ((lane & 16) ? 8 : 0);
    const int bK   = (lane & 8) ? 8 : 0;
    uint32_t bOff[NP];
#pragma unroll
    for (int p = 0; p < NP; p++)
        bOff[p] = (uint32_t)(SA_B + ((bRow + p * 16) * LDH + bK) * 2);

    float acc[4][NI][4];
#pragma unroll
    for (int i = 0; i < 4; i++)
#pragma unroll
        for (int j = 0; j < NI; j++)
#pragma unroll
            for (int r = 0; r < 4; r++) acc[i][j][r] = 0.f;

    uint32_t af[2][4][4];      // [set][mi][frag]
    uint32_t bf[2][NI][2];     // [set][ni][frag]

    auto LDFRAG = [&](int s, uint32_t stAddr, int kk) {
        const uint32_t ko = (uint32_t)(kk * 32);   // k16 step = 32 bytes
#pragma unroll
        for (int mi = 0; mi < 4; mi++)
            ldsm4(af[s][mi][0], af[s][mi][1], af[s][mi][2], af[s][mi][3],
                  stAddr + aOff[mi] + ko);
#pragma unroll
        for (int p = 0; p < NP; p++)
            ldsm4(bf[s][2 * p][0], bf[s][2 * p][1], bf[s][2 * p + 1][0], bf[s][2 * p + 1][1],
                  stAddr + bOff[p] + ko);
    };

    ISSUE(0, 0);
    ISSUE(1, 1);

    for (int kt = 0; kt < KT; ++kt) {
        const int st = kt % 3;
        cp_wait1();
        __syncthreads();
        if (kt + 2 < KT) ISSUE(kt + 2, (kt + 2) % 3);
        else cp_commit();

        const uint32_t stAddr = sbase + (uint32_t)st * SS_B;
        LDFRAG(0, stAddr, 0);
        int s = 0;
#pragma unroll
        for (int kk = 0; kk < 4; kk++) {
            if (kk < 3) LDFRAG(s ^ 1, stAddr, kk + 1);
#pragma unroll
            for (int mi = 0; mi < 4; mi++)
#pragma unroll
                for (int ni = 0; ni < NI; ni++)
                    mma_f16(acc[mi][ni], af[s][mi], bf[s][ni]);
            s ^= 1;
        }
    }

    // epilogue
#pragma unroll
    for (int mi = 0; mi < 4; mi++) {
        const size_t row = m0 + wm + mi * 16 + g;
#pragma unroll
        for (int ni = 0; ni < NI; ni++) {
            const size_t col = n0 + wn + ni * 8 + q * 2;
            if constexpr (std::is_same<OutT, float>::value) {
                *(float2*)&C[row * N + col]       = make_float2(acc[mi][ni][0], acc[mi][ni][1]);
                *(float2*)&C[(row + 8) * N + col] = make_float2(acc[mi][ni][2], acc[mi][ni][3]);
            } else {
                *(__half2*)&C[row * N + col]       = __floats2half2_rn(acc[mi][ni][0], acc[mi][ni][1]);
                *(__half2*)&C[(row + 8) * N + col] = __floats2half2_rn(acc[mi][ni][2], acc[mi][ni][3]);
            }
        }
    }
}

#define SMEM1 (3 * (SA_B + 256 * LDH * 2))   // 165888
#define SMEM2 (3 * (SA_B + 128 * LDH * 2))   // 110592

// ---------------- fp32 -> fp16 convert ----------------
__global__ void __launch_bounds__(256)
to_fp16(const float* __restrict__ in, __half* __restrict__ out, int n4)
{
    int i = blockIdx.x * 256 + threadIdx.x;
    if (i >= n4) return;
    float4 v = ((const float4*)in)[i];
    __half2* o = (__half2*)out;
    o[2 * i]     = __floats2half2_rn(v.x, v.y);
    o[2 * i + 1] = __floats2half2_rn(v.z, v.w);
}

// ---------------- GRU elementwise: a = 1-z, b = z*g(hid) ----------------
__device__ __forceinline__ void gru_ab(float hid, float gate, float& a, float& bb) {
    float e  = __expf(-fabsf(gate));
    float r  = __fdividef(1.f, 1.f + e);
    float er = e * r;
    float z  = (gate >= 0.f) ? r  : er;   // sigmoid(gate)
    float zc = (gate >= 0.f) ? er : r;    // 1 - z
    float eh = __expf(fminf(hid, 0.f));
    float gv = (hid >= 0.f) ? (hid + 0.5f) : __fdividef(eh, 1.f + eh);
    a = zc; bb = z * gv;
}

// phase 1: one ascending pass -> fwd (A,B) and bwd (A,B) chunk summaries. half2 lanes.
__global__ void __launch_bounds__(256) scan_p1() {
    const int e2 = blockIdx.x * 256 + threadIdx.x;   // 0 .. EI/2-1
    const int e  = e2 * 2;
    const int c  = blockIdx.y;
    const int b  = blockIdx.z;
    const __half2* __restrict__ base =
        (const __half2*)(g_hg + ((size_t)b * SLEN + (size_t)c * CL) * HGW + e);
    float2 hF = {0.f, 0.f}, P = {1.f, 1.f}, Bb = {0.f, 0.f};
#pragma unroll 4
    for (int i = 0; i < CL; i++) {
        float2 hid  = __half22float2(base[0]);
        float2 gate = __half22float2(base[EI / 2]);
        base += HGW / 2;
        float a0, b0, a1, b1;
        gru_ab(hid.x, gate.x, a0, b0);
        gru_ab(hid.y, gate.y, a1, b1);
        hF.x = fmaf(a0, hF.x, b0);  hF.y = fmaf(a1, hF.y, b1);
        Bb.x = fmaf(b0, P.x, Bb.x); Bb.y = fmaf(b1, P.y, Bb.y);
        P.x *= a0; P.y *= a1;
    }
    size_t f = (((size_t)b) * NC + c) * EI + e;                       // fwd chunk c
    size_t r = (((size_t)(BDIM + b)) * NC + (NC - 1 - c)) * EI + e;   // bwd traversal chunk
    *(float2*)&g_cA[f] = P;  *(float2*)&g_cB[f] = hF;
    *(float2*)&g_cA[r] = P;  *(float2*)&g_cB[r] = Bb;
}

// phase 2: scan the NC chunk summaries per (dir,b,e)
__global__ void __launch_bounds__(256) scan_p2() {
    int t  = blockIdx.x * 256 + threadIdx.x;   // 0 .. 2*BDIM*EI-1
    int db = t / EI;
    int e  = t - db * EI;
    float h = 0.f;
    for (int c = 0; c < NC; c++) {
        size_t ci = ((size_t)db * NC + c) * EI + e;
        g_cI[ci] = h;
        h = fmaf(g_cA[ci], h, g_cB[ci]);
    }
}

// phase 3: fused fwd+bwd apply, writes hsum = hf+hb as fp16. half2 lanes.
__global__ void __launch_bounds__(256) scan_p3() {
    const int e2 = blockIdx.x * 256 + threadIdx.x;
    const int e  = e2 * 2;
    const int c  = blockIdx.y;
    const int b  = blockIdx.z;
    const __half2* __restrict__ bF =
        (const __half2*)(g_hg + ((size_t)b * SLEN + (size_t)c * CL) * HGW + e);
    const __half2* __restrict__ bB =
        (const __half2*)(g_hg + ((size_t)b * SLEN + (size_t)(SLEN - 1 - c * CL)) * HGW + e);
    float2 hF = *(const float2*)&g_cI[(((size_t)b) * NC + c) * EI + e];
    float2 hB = *(const float2*)&g_cI[(((size_t)(BDIM + b)) * NC + c) * EI + e];
    __half2* outp = (__half2*)(g_hsh + ((size_t)b * SLEN + (size_t)c * CL) * EI + e);
#pragma unroll 4
    for (int i = 0; i < CL; i++) {
        float2 hidF = __half22float2(bF[0]), gateF = __half22float2(bF[EI / 2]);
        float2 hidB = __half22float2(bB[0]), gateB = __half22float2(bB[EI / 2]);
        bF += HGW / 2; bB -= HGW / 2;
        float a0, b0;
        gru_ab(hidF.x, gateF.x, a0, b0); hF.x = fmaf(a0, hF.x, b0);
        gru_ab(hidF.y, gateF.y, a0, b0); hF.y = fmaf(a0, hF.y, b0);
        gru_ab(hidB.x, gateB.x, a0, b0); hB.x = fmaf(a0, hB.x, b0);
        gru_ab(hidB.y, gateB.y, a0, b0); hB.y = fmaf(a0, hB.y, b0);
        *outp = __floats2half2_rn(hF.x + hB.x, hF.y + hB.y);
        outp += EI / 2;
    }
}

// ---------------- launch ----------------
extern "C" void kernel_launch(void* const* d_in, const int* in_sizes, int n_in,
                              void* d_out, int out_size)
{
    const float* x    = (const float*)d_in[0];   // [4,4096,1024]
    const float* Whg  = (const float*)d_in[1];   // [3072,1024]
    const float* Wout = (const float*)d_in[2];   // [1024,1536]
    float* out = (float*)d_out;                  // [4,4096,1024]

    void *hg, *xh, *wh, *uh, *hsh;
    cudaGetSymbolAddress(&hg,  g_hg);
    cudaGetSymbolAddress(&xh,  g_xh);
    cudaGetSymbolAddress(&wh,  g_wh);
    cudaGetSymbolAddress(&uh,  g_uh);
    cudaGetSymbolAddress(&hsh, g_hsh);

    cudaFuncSetAttribute(gemm_fp16<256, __half>, cudaFuncAttributeMaxDynamicSharedMemorySize, SMEM1);
    cudaFuncSetAttribute(gemm_fp16<128, float>,  cudaFuncAttributeMaxDynamicSharedMemorySize, SMEM2);

    // convert operands to fp16 once
    to_fp16<<<(MTOT * DIMX / 4 + 255) / 256, 256>>>(x,    (__half*)xh, MTOT * DIMX / 4);
    to_fp16<<<(HGW * DIMX / 4 + 255) / 256, 256>>>(Whg,  (__half*)wh, HGW * DIMX / 4);
    to_fp16<<<(DIMX * EI / 4 + 255) / 256, 256>>>(Wout, (__half*)uh, DIMX * EI / 4);

    // GEMM1: hg[16384,3072] = x @ W_hg^T  (K = 1024), fp16 output, BN=256
    gemm_fp16<256, __half><<<dim3(HGW / 256, MTOT / GBM), 256, SMEM1>>>(
        (const __half*)xh, (const __half*)wh, (__half*)hg, HGW, DIMX);

    // bidirectional blocked scan (fused dirs, half2-vectorized)
    scan_p1<<<dim3(EI / 512, NC, BDIM), 256>>>();
    scan_p2<<<dim3((2 * BDIM * EI) / 256), 256>>>();
    scan_p3<<<dim3(EI / 512, NC, BDIM), 256>>>();

    // GEMM2: out[16384,1024] = hsum @ W_out^T  (K = 1536), fp32 output, BN=128 (tail fix)
    gemm_fp16<128, float><<<dim3(DIMX / 128, MTOT / GBM), 256, SMEM2>>>(
        (const __half*)hsh, (const __half*)uh, out, DIMX, EI);
}

// round 17
// speedup vs baseline: 1.0812x; 1.0812x over previous
#include <cuda_runtime.h>
#include <cuda_fp16.h>
#include <cstdint>
#include <cstddef>
#include <type_traits>

// ---------------- problem constants ----------------
#define BDIM 4
#define SLEN 4096
#define DIMX 1024
#define EI   1536
#define HGW  3072
#define NC   64
#define CL   64               // SLEN/NC
#define MTOT (BDIM*SLEN)      // 16384

// ---------------- scratch (device globals; no allocation) ----------------
__device__ __half g_hg [(size_t)MTOT * HGW];   // GEMM1 output [16384,3072] fp16
__device__ __half g_xh [(size_t)MTOT * DIMX];  // fp16 x
__device__ __half g_wh [(size_t)HGW * DIMX];   // fp16 W_hg
__device__ __half g_uh [(size_t)DIMX * EI];    // fp16 W_out
__device__ __half g_hsh[(size_t)MTOT * EI];    // fp16 hsum = hf+hb
__device__ float  g_cA[2 * BDIM * NC * EI];
__device__ float  g_cB[2 * BDIM * NC * EI];
__device__ float  g_cI[2 * BDIM * NC * EI];

// ---------------- helpers ----------------
__device__ __forceinline__ uint32_t s2u(const void* p) {
    uint32_t a;
    asm("{ .reg .u64 t; cvta.to.shared.u64 t, %1; cvt.u32.u64 %0, t; }" : "=r"(a) : "l"(p));
    return a;
}
__device__ __forceinline__ void cp16(uint32_t dst, const void* src) {
    asm volatile("cp.async.cg.shared.global [%0], [%1], 16;" :: "r"(dst), "l"(src) : "memory");
}
__device__ __forceinline__ void cp_commit() {
    asm volatile("cp.async.commit_group;" ::: "memory");
}
__device__ __forceinline__ void cp_wait1() {
    asm volatile("cp.async.wait_group 1;" ::: "memory");
}
__device__ __forceinline__ void mma_f16(float c[4], const uint32_t a[4], const uint32_t b[2]) {
    asm volatile(
        "mma.sync.aligned.m16n8k16.row.col.f32.f16.f16.f32 "
        "{%0,%1,%2,%3}, {%4,%5,%6,%7}, {%8,%9}, {%0,%1,%2,%3};\n"
        : "+f"(c[0]), "+f"(c[1]), "+f"(c[2]), "+f"(c[3])
        : "r"(a[0]), "r"(a[1]), "r"(a[2]), "r"(a[3]), "r"(b[0]), "r"(b[1]));
}
__device__ __forceinline__ void ldsm4(uint32_t& d0, uint32_t& d1, uint32_t& d2, uint32_t& d3,
                                      uint32_t a) {
    asm volatile("ldmatrix.sync.aligned.m8n8.x4.shared.b16 {%0,%1,%2,%3}, [%4];"
                 : "=r"(d0), "=r"(d1), "=r"(d2), "=r"(d3) : "r"(a));
}

// ---------------- GEMM: C[M,N] = A[M,K] * B[N,K]^T  (fp16 operands, fp32 accum)
// BM=128, BN=256, BK=64 halfs, 3-stage cp.async pipeline, 256 threads = 8 warps of 64x64.
// Fragments via ldmatrix.x4, double-buffered across k16 steps. (R6/R13 proven config.)
#define GBM 128
#define GBN 256
#define GBK 64                          // halfs per K block (128 bytes)
#define LDH 72                          // halfs per smem row (144B)
#define SA_B (GBM * LDH * 2)            // 18432 B
#define SB_B (GBN * LDH * 2)            // 36864 B
#define SS_B (SA_B + SB_B)              // 55296 B per stage
#define SMEM_BYTES (3 * SS_B)           // 165888

template <typename OutT>
__global__ void __launch_bounds__(256, 1)
gemm_fp16(const __half* __restrict__ A, const __half* __restrict__ B,
          OutT* __restrict__ C, int N, int K)
{
    extern __shared__ __align__(16) char smc[];
    const uint32_t sbase = s2u(smc);

    const int tid  = threadIdx.x;
    const int lane = tid & 31;
    const int warp = tid >> 5;
    const int wm = (warp >> 2) << 6;   // 0, 64
    const int wn = (warp & 3) << 6;    // 0, 64, 128, 192
    const int g  = lane >> 2;
    const int q  = lane & 3;

    const int m0 = blockIdx.y << 7;
    const int n0 = blockIdx.x << 8;
    const int KT = K >> 6;             // K / 64

    const int arow = tid >> 3;          // 0..31
    const int chk  = tid & 7;
    const __half* Abase = A + (size_t)(m0 + arow) * K + chk * 8;
    const __half* Bbase = B + (size_t)(n0 + arow) * K + chk * 8;

    auto ISSUE = [&](int kt, int st) {
        const uint32_t sa = sbase + (uint32_t)st * SS_B;
        const uint32_t sb = sa + SA_B;
        const size_t ko = (size_t)kt * GBK;
#pragma unroll
        for (int j = 0; j < 4; j++)
            cp16(sa + (uint32_t)((arow + 32 * j) * LDH + chk * 8) * 2,
                 Abase + (size_t)(32 * j) * K + ko);
#pragma unroll
        for (int j = 0; j < 8; j++)
            cp16(sb + (uint32_t)((arow + 32 * j) * LDH + chk * 8) * 2,
                 Bbase + (size_t)(32 * j) * K + ko);
        cp_commit();
    };

    // ldmatrix per-lane base byte offsets (relative to stage base)
    const int aRow = wm + (lane & 15);
    const int aK   = (lane & 16) ? 8 : 0;
    uint32_t aOff[4];
#pragma unroll
    for (int mi = 0; mi < 4; mi++)
        aOff[mi] = (uint32_t)(((aRow + mi * 16) * LDH + aK) * 2);
    const int bRow = wn + (lane & 7) + ((lane & 16) ? 8 : 0);
    const int bK   = (lane & 8) ? 8 : 0;
    uint32_t bOff[4];
#pragma unroll
    for (int p = 0; p < 4; p++)
        bOff[p] = (uint32_t)(SA_B + ((bRow + p * 16) * LDH + bK) * 2);

    float acc[4][8][4];
#pragma unroll
    for (int i = 0; i < 4; i++)
#pragma unroll
        for (int j = 0; j < 8; j++)
#pragma unroll
            for (int r = 0; r < 4; r++) acc[i][j][r] = 0.f;

    uint32_t af[2][4][4];     // [set][mi][frag]
    uint32_t bf[2][8][2];     // [set][ni][frag]

    auto LDFRAG = [&](int s, uint32_t stAddr, int kk) {
        const uint32_t ko = (uint32_t)(kk * 32);   // k16 step = 32 bytes
#pragma unroll
        for (int mi = 0; mi < 4; mi++)
            ldsm4(af[s][mi][0], af[s][mi][1], af[s][mi][2], af[s][mi][3],
                  stAddr + aOff[mi] + ko);
#pragma unroll
        for (int p = 0; p < 4; p++)
            ldsm4(bf[s][2 * p][0], bf[s][2 * p][1], bf[s][2 * p + 1][0], bf[s][2 * p + 1][1],
                  stAddr + bOff[p] + ko);
    };

    ISSUE(0, 0);
    ISSUE(1, 1);

    for (int kt = 0; kt < KT; ++kt) {
        const int st = kt % 3;
        cp_wait1();
        __syncthreads();
        if (kt + 2 < KT) ISSUE(kt + 2, (kt + 2) % 3);
        else cp_commit();

        const uint32_t stAddr = sbase + (uint32_t)st * SS_B;
        LDFRAG(0, stAddr, 0);
        int s = 0;
#pragma unroll
        for (int kk = 0; kk < 4; kk++) {
            if (kk < 3) LDFRAG(s ^ 1, stAddr, kk + 1);
#pragma unroll
            for (int mi = 0; mi < 4; mi++)
#pragma unroll
                for (int ni = 0; ni < 8; ni++)
                    mma_f16(acc[mi][ni], af[s][mi], bf[s][ni]);
            s ^= 1;
        }
    }

    // epilogue
#pragma unroll
    for (int mi = 0; mi < 4; mi++) {
        const size_t row = m0 + wm + mi * 16 + g;
#pragma unroll
        for (int ni = 0; ni < 8; ni++) {
            const size_t col = n0 + wn + ni * 8 + q * 2;
            if constexpr (std::is_same<OutT, float>::value) {
                *(float2*)&C[row * N + col]       = make_float2(acc[mi][ni][0], acc[mi][ni][1]);
                *(float2*)&C[(row + 8) * N + col] = make_float2(acc[mi][ni][2], acc[mi][ni][3]);
            } else {
                *(__half2*)&C[row * N + col]       = __floats2half2_rn(acc[mi][ni][0], acc[mi][ni][1]);
                *(__half2*)&C[(row + 8) * N + col] = __floats2half2_rn(acc[mi][ni][2], acc[mi][ni][3]);
            }
        }
    }
}

// ---------------- fp32 -> fp16 convert ----------------
__global__ void __launch_bounds__(256)
to_fp16(const float* __restrict__ in, __half* __restrict__ out, int n4)
{
    int i = blockIdx.x * 256 + threadIdx.x;
    if (i >= n4) return;
    float4 v = ((const float4*)in)[i];
    __half2* o = (__half2*)out;
    o[2 * i]     = __floats2half2_rn(v.x, v.y);
    o[2 * i + 1] = __floats2half2_rn(v.z, v.w);
}

// ---------------- GRU elementwise: a = 1-z, b = z*g(hid) ----------------
__device__ __forceinline__ void gru_ab(float hid, float gate, float& a, float& bb) {
    float e  = __expf(-fabsf(gate));
    float r  = __fdividef(1.f, 1.f + e);
    float er = e * r;
    float z  = (gate >= 0.f) ? r  : er;   // sigmoid(gate)
    float zc = (gate >= 0.f) ? er : r;    // 1 - z
    float eh = __expf(fminf(hid, 0.f));
    float gv = (hid >= 0.f) ? (hid + 0.5f) : __fdividef(eh, 1.f + eh);
    a = zc; bb = z * gv;
}

// phase 1: one ascending pass -> fwd (A,B) and bwd (A,B) chunk summaries.
// half2 lanes; grid kept at 768 blocks via NC=64 (CL=64).
__global__ void __launch_bounds__(256) scan_p1() {
    const int t  = blockIdx.x * 256 + threadIdx.x;   // 0 .. EI/2-1 (768)
    const int e  = t * 2;
    const int c  = blockIdx.y;
    const int b  = blockIdx.z;
    const __half2* __restrict__ base =
        (const __half2*)(g_hg + ((size_t)b * SLEN + (size_t)c * CL) * HGW + e);
    float2 hF = {0.f, 0.f}, P = {1.f, 1.f}, Bb = {0.f, 0.f};
#pragma unroll 4
    for (int i = 0; i < CL; i++) {
        float2 hid  = __half22float2(base[0]);
        float2 gate = __half22float2(base[EI / 2]);
        base += HGW / 2;
        float a0, b0, a1, b1;
        gru_ab(hid.x, gate.x, a0, b0);
        gru_ab(hid.y, gate.y, a1, b1);
        hF.x = fmaf(a0, hF.x, b0);  hF.y = fmaf(a1, hF.y, b1);
        Bb.x = fmaf(b0, P.x, Bb.x); Bb.y = fmaf(b1, P.y, Bb.y);
        P.x *= a0; P.y *= a1;
    }
    size_t f = (((size_t)b) * NC + c) * EI + e;                       // fwd chunk c
    size_t r = (((size_t)(BDIM + b)) * NC + (NC - 1 - c)) * EI + e;   // bwd traversal chunk
    *(float2*)&g_cA[f] = P;  *(float2*)&g_cB[f] = hF;
    *(float2*)&g_cA[r] = P;  *(float2*)&g_cB[r] = Bb;
}

// phase 2: scan the NC chunk summaries per (dir,b,e)
__global__ void __launch_bounds__(256) scan_p2() {
    int t  = blockIdx.x * 256 + threadIdx.x;   // 0 .. 2*BDIM*EI-1
    int db = t / EI;
    int e  = t - db * EI;
    float h = 0.f;
    for (int c = 0; c < NC; c++) {
        size_t ci = ((size_t)db * NC + c) * EI + e;
        g_cI[ci] = h;
        h = fmaf(g_cA[ci], h, g_cB[ci]);
    }
}

// phase 3: fused fwd+bwd apply, writes hsum = hf+hb as half2.
__global__ void __launch_bounds__(256) scan_p3() {
    const int t  = blockIdx.x * 256 + threadIdx.x;   // 0 .. EI/2-1
    const int e  = t * 2;
    const int c  = blockIdx.y;
    const int b  = blockIdx.z;
    const __half2* __restrict__ bF =
        (const __half2*)(g_hg + ((size_t)b * SLEN + (size_t)c * CL) * HGW + e);
    const __half2* __restrict__ bB =
        (const __half2*)(g_hg + ((size_t)b * SLEN + (size_t)(SLEN - 1 - c * CL)) * HGW + e);
    float2 hF = *(const float2*)&g_cI[(((size_t)b) * NC + c) * EI + e];
    float2 hB = *(const float2*)&g_cI[(((size_t)(BDIM + b)) * NC + c) * EI + e];
    __half2* outp = (__half2*)(g_hsh + ((size_t)b * SLEN + (size_t)c * CL) * EI + e);
#pragma unroll 4
    for (int i = 0; i < CL; i++) {
        float2 hidF = __half22float2(bF[0]), gateF = __half22float2(bF[EI / 2]);
        float2 hidB = __half22float2(bB[0]), gateB = __half22float2(bB[EI / 2]);
        bF += HGW / 2; bB -= HGW / 2;
        float a0, b0;
        gru_ab(hidF.x, gateF.x, a0, b0); hF.x = fmaf(a0, hF.x, b0);
        gru_ab(hidF.y, gateF.y, a0, b0); hF.y = fmaf(a0, hF.y, b0);
        gru_ab(hidB.x, gateB.x, a0, b0); hB.x = fmaf(a0, hB.x, b0);
        gru_ab(hidB.y, gateB.y, a0, b0); hB.y = fmaf(a0, hB.y, b0);
        *outp = __floats2half2_rn(hF.x + hB.x, hF.y + hB.y);
        outp += EI / 2;
    }
}

// ---------------- launch ----------------
extern "C" void kernel_launch(void* const* d_in, const int* in_sizes, int n_in,
                              void* d_out, int out_size)
{
    const float* x    = (const float*)d_in[0];   // [4,4096,1024]
    const float* Whg  = (const float*)d_in[1];   // [3072,1024]
    const float* Wout = (const float*)d_in[2];   // [1024,1536]
    float* out = (float*)d_out;                  // [4,4096,1024]

    void *hg, *xh, *wh, *uh, *hsh;
    cudaGetSymbolAddress(&hg,  g_hg);
    cudaGetSymbolAddress(&xh,  g_xh);
    cudaGetSymbolAddress(&wh,  g_wh);
    cudaGetSymbolAddress(&uh,  g_uh);
    cudaGetSymbolAddress(&hsh, g_hsh);

    cudaFuncSetAttribute(gemm_fp16<__half>, cudaFuncAttributeMaxDynamicSharedMemorySize, SMEM_BYTES);
    cudaFuncSetAttribute(gemm_fp16<float>,  cudaFuncAttributeMaxDynamicSharedMemorySize, SMEM_BYTES);

    // convert operands to fp16 once
    to_fp16<<<(MTOT * DIMX / 4 + 255) / 256, 256>>>(x,    (__half*)xh, MTOT * DIMX / 4);
    to_fp16<<<(HGW * DIMX / 4 + 255) / 256, 256>>>(Whg,  (__half*)wh, HGW * DIMX / 4);
    to_fp16<<<(DIMX * EI / 4 + 255) / 256, 256>>>(Wout, (__half*)uh, DIMX * EI / 4);

    // GEMM1: hg[16384,3072] = x @ W_hg^T  (K = 1024), fp16 output
    gemm_fp16<__half><<<dim3(HGW / GBN, MTOT / GBM), 256, SMEM_BYTES>>>(
        (const __half*)xh, (const __half*)wh, (__half*)hg, HGW, DIMX);

    // bidirectional blocked scan (fused dirs, half2 lanes, NC=64 keeps 196K threads)
    scan_p1<<<dim3(EI / 512, NC, BDIM), 256>>>();
    scan_p2<<<dim3((2 * BDIM * EI) / 256), 256>>>();
    scan_p3<<<dim3(EI / 512, NC, BDIM), 256>>>();

    // GEMM2: out[16384,1024] = hsum @ W_out^T  (K = 1536), fp32 output, BN=256
    gemm_fp16<float><<<dim3(DIMX / GBN, MTOT / GBM), 256, SMEM_BYTES>>>(
        (const __half*)hsh, (const __half*)uh, out, DIMX, EI);
}